// round 10
// baseline (speedup 1.0000x reference)
#include <cuda_runtime.h>
#include <cstdint>

// PatchEmbedding: x(1,3,384,384) f32, W(768,12), b(768), positions(768,146689)
// out[e,l] = b[e] + positions[e,l] + sum_d patch[d,l] * W[e,d]
//
// pos streamed into smem by a single-thread cp.async.bulk + mbarrier ring
// (engine-driven MLP, zero register cost). Math done in packed f32x2
// (FFMA2): each thread computes the adjacent pair (l, l+1).

#define IMG      384
#define LW       383
#define L_TOTAL  146689              // 383*383
#define EMB      768
#define PD       12

#define TPB      256
#define L_TILE   (2 * TPB)           // 512 l per block (adjacent pairs)
#define E_TILE   64                  // 768/64 = 12 y-blocks
#define CH       8                   // e-rows per stage
#define NCH      (E_TILE / CH)       // 8
#define NSTAGE   2                   // ring depth

// Stage row: 520 floats (2080B, 16B multiple). gmem copy starts at
// rowstart - (e&3) floats so the bulk source is 16B-aligned; data for the
// block's 512 l sits at smem float offset (e&3)..(e&3)+511 < 520.
#define ROWF     520
#define ROWB     (ROWF * 4)          // 2080
#define STAGEF   (CH * ROWF)         // 4160 floats
#define STAGEB   (CH * ROWB)         // 16640 bytes

typedef unsigned long long ull;

__device__ __forceinline__ ull mul2(ull a, ull b) {
    ull d; asm("mul.rn.f32x2 %0, %1, %2;" : "=l"(d) : "l"(a), "l"(b)); return d;
}
__device__ __forceinline__ ull fma2(ull a, ull b, ull c) {
    ull d; asm("fma.rn.f32x2 %0, %1, %2, %3;" : "=l"(d) : "l"(a), "l"(b), "l"(c)); return d;
}
__device__ __forceinline__ ull add2(ull a, ull b) {
    ull d; asm("add.rn.f32x2 %0, %1, %2;" : "=l"(d) : "l"(a), "l"(b)); return d;
}
__device__ __forceinline__ ull pack2(float lo, float hi) {
    ull r; asm("mov.b64 %0, {%1, %2};" : "=l"(r) : "f"(lo), "f"(hi)); return r;
}
__device__ __forceinline__ void unpack2(ull v, float& lo, float& hi) {
    asm("mov.b64 {%0, %1}, %2;" : "=f"(lo), "=f"(hi) : "l"(v));
}

__device__ __forceinline__ void gather_patch(const float* __restrict__ x,
                                             int l, float* p) {
    const int r   = l / LW;
    const int col = l - r * LW;
    const float* xp = x + r * IMG + col;
    #pragma unroll
    for (int c = 0; c < 3; c++)
        #pragma unroll
        for (int i = 0; i < 2; i++)
            #pragma unroll
            for (int j = 0; j < 2; j++)
                p[c * 4 + i * 2 + j] = xp[c * IMG * IMG + i * IMG + j];
}

__device__ __forceinline__ void mbar_init(uint32_t bar, uint32_t cnt) {
    asm volatile("mbarrier.init.shared.b64 [%0], %1;" :: "r"(bar), "r"(cnt) : "memory");
}
__device__ __forceinline__ void mbar_expect_tx(uint32_t bar, uint32_t bytes) {
    asm volatile("mbarrier.arrive.expect_tx.shared.b64 _, [%0], %1;"
                 :: "r"(bar), "r"(bytes) : "memory");
}
__device__ __forceinline__ void mbar_arrive(uint32_t bar) {
    asm volatile("mbarrier.arrive.shared.b64 _, [%0];" :: "r"(bar) : "memory");
}
__device__ __forceinline__ void mbar_wait(uint32_t bar, uint32_t parity) {
    asm volatile(
        "{\n\t.reg .pred P;\n\t"
        "W%=:\n\t"
        "mbarrier.try_wait.parity.shared.b64 P, [%0], %1, 0x989680;\n\t"
        "@P bra.uni D%=;\n\t"
        "bra.uni W%=;\n\t"
        "D%=:\n\t}"
        :: "r"(bar), "r"(parity) : "memory");
}
__device__ __forceinline__ void bulk_cp(uint32_t dst, const float* src,
                                        uint32_t bar) {
    asm volatile(
        "cp.async.bulk.shared::cta.global.mbarrier::complete_tx::bytes "
        "[%0], [%1], %2, [%3];"
        :: "r"(dst), "l"(src), "r"((uint32_t)ROWB), "r"(bar) : "memory");
}

__global__ __launch_bounds__(TPB, 4)
void patch_embed_kernel(const float* __restrict__ x,
                        const float* __restrict__ W,
                        const float* __restrict__ b,
                        const float* __restrict__ pos,
                        float* __restrict__ out) {
    __shared__ __align__(16) float spv[NSTAGE * STAGEF];   // 33,280 B
    __shared__ __align__(16) ull   sW2[E_TILE * PD];       // 6,144 B ({w,w} pairs)
    __shared__ ull                 sB2[E_TILE];            // 512 B
    __shared__ __align__(8)  ull   mbar[2 * NSTAGE];

    const int e0 = blockIdx.y * E_TILE;
    const int l0 = blockIdx.x * L_TILE;
    const bool full = (blockIdx.x != gridDim.x - 1);

    // Stage W (duplicated pairs) + b into smem.
    for (int i = threadIdx.x; i < E_TILE * PD; i += TPB) {
        const float w = W[e0 * PD + i];
        sW2[i] = pack2(w, w);
    }
    if (threadIdx.x < E_TILE) {
        const float bv = b[e0 + threadIdx.x];
        sB2[threadIdx.x] = pack2(bv, bv);
    }

    const uint32_t sbase = (uint32_t)__cvta_generic_to_shared(spv);
    const uint32_t bbase = (uint32_t)__cvta_generic_to_shared(mbar);
    #define FULLB(s)  (bbase + (uint32_t)(s) * 8u)
    #define EMPTYB(s) (bbase + (uint32_t)(NSTAGE + (s)) * 8u)

    if (full && threadIdx.x == 0) {
        #pragma unroll
        for (int s = 0; s < NSTAGE; s++) {
            mbar_init(FULLB(s), 1);
            mbar_init(EMPTYB(s), TPB);
        }
        asm volatile("fence.proxy.async.shared::cta;" ::: "memory");
    }
    __syncthreads();

    if (!full) {
        // ---- tail x-block: 257 valid l; scalar path, direct loads ----
        const float* sWf = (const float*)sW2;   // duplicated pairs: idx*2
        #pragma unroll 1
        for (int k = 0; k < 2; k++) {
            const int l = l0 + 2 * threadIdx.x + k;
            if (l >= L_TOTAL) continue;
            float p[PD];
            gather_patch(x, l, p);
            for (int ee = 0; ee < E_TILE; ee++) {
                const int e = e0 + ee;
                float c0 = p[0] * sWf[(ee * PD + 0) * 2];
                float c1 = p[1] * sWf[(ee * PD + 1) * 2];
                #pragma unroll
                for (int d = 2; d < PD; d += 2) {
                    c0 = fmaf(p[d],     sWf[(ee * PD + d) * 2],     c0);
                    c1 = fmaf(p[d + 1], sWf[(ee * PD + d + 1) * 2], c1);
                }
                float blo, bhi;
                unpack2(sB2[ee], blo, bhi);
                const float pvv = pos[(size_t)e * L_TOTAL + l];
                out[(size_t)e * L_TOTAL + l] = (blo + pvv) + (c0 + c1);
            }
        }
        return;
    }

    // ---- full blocks ----
    // Gather adjacent patch pair, packed.
    const int la = l0 + 2 * threadIdx.x;
    ull p2[PD];
    {
        float pa[PD], pb[PD];
        gather_patch(x, la, pa);
        gather_patch(x, la + 1, pb);
        #pragma unroll
        for (int d = 0; d < PD; d++)
            p2[d] = pack2(pa[d], pb[d]);
    }

    // Prologue: fill stage 0 (rows e0..e0+7).
    if (threadIdx.x == 0) {
        mbar_expect_tx(FULLB(0), STAGEB);
        #pragma unroll
        for (int j = 0; j < CH; j++)
            bulk_cp(sbase + (uint32_t)(j * ROWB),
                    pos + (size_t)(e0 + j) * L_TOTAL + l0 - (j & 3),
                    FULLB(0));
    }

    #pragma unroll
    for (int cc = 0; cc < NCH; cc++) {
        // Producer: fill stage cc+1.
        if (threadIdx.x == 0) {
            const int s = cc + 1;
            if (s < NCH) {
                const int st = s & 1;
                const int k  = s >> 1;
                if (k > 0)
                    mbar_wait(EMPTYB(st), (uint32_t)((k - 1) & 1));
                mbar_expect_tx(FULLB(st), STAGEB);
                #pragma unroll
                for (int j = 0; j < CH; j++)
                    bulk_cp(sbase + (uint32_t)(st * STAGEB + j * ROWB),
                            pos + (size_t)(e0 + s * CH + j) * L_TOTAL + l0 - (j & 3),
                            FULLB(st));
            }
        }

        const int st = cc & 1;
        mbar_wait(FULLB(st), (uint32_t)((cc >> 1) & 1));

        #pragma unroll
        for (int j = 0; j < CH; j++) {
            const int ee = cc * CH + j;
            const int e  = e0 + ee;
            const ull* w = &sW2[ee * PD];

            // pos pair from smem. Even j (even e): 8B-aligned -> LDS.64.
            const int off = st * STAGEF + j * ROWF + (j & 3) + 2 * threadIdx.x;
            ull pv;
            if ((j & 1) == 0) pv = *(const ull*)&spv[off];
            else              pv = pack2(spv[off], spv[off + 1]);

            // Two depth-6 packed chains.
            ull ca = mul2(p2[0], w[0]);
            ull cb = mul2(p2[1], w[1]);
            ca = fma2(p2[2],  w[2],  ca);  cb = fma2(p2[3],  w[3],  cb);
            ca = fma2(p2[4],  w[4],  ca);  cb = fma2(p2[5],  w[5],  cb);
            ca = fma2(p2[6],  w[6],  ca);  cb = fma2(p2[7],  w[7],  cb);
            ca = fma2(p2[8],  w[8],  ca);  cb = fma2(p2[9],  w[9],  cb);
            ca = fma2(p2[10], w[10], ca);  cb = fma2(p2[11], w[11], cb);

            const ull res = add2(add2(ca, cb), add2(sB2[ee], pv));

            float* op = out + (size_t)e * L_TOTAL + la;
            if ((j & 1) == 0) {
                // e even -> (e*L + la) even -> 8B-aligned vector store.
                __stcs((double*)op, __longlong_as_double((long long)res));
            } else {
                float o0, o1;
                unpack2(res, o0, o1);
                __stcs(op,     o0);
                __stcs(op + 1, o1);
            }
        }

        mbar_arrive(EMPTYB(st));
    }
}

extern "C" void kernel_launch(void* const* d_in, const int* in_sizes, int n_in,
                              void* d_out, int out_size) {
    const float* x   = (const float*)d_in[0];
    const float* W   = (const float*)d_in[1];
    const float* b   = (const float*)d_in[2];
    const float* pos = (const float*)d_in[3];
    float* out = (float*)d_out;

    dim3 grid((L_TOTAL + L_TILE - 1) / L_TILE,   // 287 (last = tail path)
              EMB / E_TILE,                      // 12
              1);
    patch_embed_kernel<<<grid, TPB>>>(x, W, b, pos, out);
}